// round 7
// baseline (speedup 1.0000x reference)
#include <cuda_runtime.h>
#include <cuda_bf16.h>
#include <cstdint>

// TransINT scoring, single-pass quadratic form.
//   re = heads[rel2head[r]] * rel2mult[r]        (r = pos_r; neg_r unused)
//   s_pos = ent[ph] + re - ent[pt];  s_neg = ent[nh] + re - ent[nt]
//   A = bases[r] (2 x 256); c = ATA^{-1} (A.s)
//   exact-solution identity: ||s - A^T c||^2 = s.s - c.(A.s)
// out[0:B) = pos, out[B:2B) = neg (float32)
//
// Memory scheme: 32-bit scalar loads, lane L reads element L + 32k.
// Every warp access is exactly one 128B line = one L1tex wavefront at the
// 1.0 cyc/wf cross-LDG rate (LDG.128 over 512B costs 1 + 3 replays @2.07).
// 56 loads/sample -> ~58 L1tex cyc/sample vs ~101 for the float4 version.

#define D 256
#define WARPS_PER_BLOCK 8

typedef unsigned long long ull;

__device__ __forceinline__ ull pack2(float lo, float hi) {
    ull r;
    asm("mov.b64 %0, {%1, %2};" : "=l"(r) : "f"(lo), "f"(hi));
    return r;
}
__device__ __forceinline__ void unpack2(ull v, float& lo, float& hi) {
    asm("mov.b64 {%0, %1}, %2;" : "=f"(lo), "=f"(hi) : "l"(v));
}
__device__ __forceinline__ ull ffma2(ull a, ull b, ull c) {
    ull d;
    asm("fma.rn.f32x2 %0, %1, %2, %3;" : "=l"(d) : "l"(a), "l"(b), "l"(c));
    return d;
}
__device__ __forceinline__ float pair_sum(ull v) {
    float lo, hi;
    unpack2(v, lo, hi);
    return lo + hi;
}

__global__ __launch_bounds__(WARPS_PER_BLOCK * 32, 5)
void transint_kernel(const int* __restrict__ pos_h,
                     const int* __restrict__ pos_t,
                     const int* __restrict__ pos_r,
                     const int* __restrict__ neg_h,
                     const int* __restrict__ neg_t,
                     const float* __restrict__ ent_emb,   // E x D
                     const float* __restrict__ heads,     // K x D
                     const float* __restrict__ bases,     // R x 2 x D
                     const int* __restrict__ rel2head,
                     const float* __restrict__ rel2mult,
                     float* __restrict__ out,
                     int B)
{
    const int warp = blockIdx.x * WARPS_PER_BLOCK + (threadIdx.x >> 5);
    if (warp >= B) return;
    const int lane = threadIdx.x & 31;

    // Per-sample indices (uniform across warp; broadcast loads)
    const int ph = pos_h[warp];
    const int pt = pos_t[warp];
    const int r  = pos_r[warp];
    const int nh = neg_h[warp];
    const int nt = neg_t[warp];
    const int hd = rel2head[r];
    const float mult = rel2mult[r];

    const float* __restrict__ Eph = ent_emb + (size_t)ph * D + lane;
    const float* __restrict__ Ept = ent_emb + (size_t)pt * D + lane;
    const float* __restrict__ Enh = ent_emb + (size_t)nh * D + lane;
    const float* __restrict__ Ent = ent_emb + (size_t)nt * D + lane;
    const float* __restrict__ Hd  = heads   + (size_t)hd * D + lane;
    const float* __restrict__ B0  = bases   + (size_t)r * 2 * D + lane;
    const float* __restrict__ B1  = bases   + (size_t)r * 2 * D + D + lane;

    // 56 scalar loads, all independent -> full MLP; each warp access = 1 line
    float hp[8], tp[8], hn[8], tn[8], hh[8], a0[8], a1[8];
    #pragma unroll
    for (int k = 0; k < 8; k++) {
        hp[k] = Eph[32 * k];
        tp[k] = Ept[32 * k];
        hn[k] = Enh[32 * k];
        tn[k] = Ent[32 * k];
        hh[k] = Hd [32 * k];
        a0[k] = B0 [32 * k];
        a1[k] = B1 [32 * k];
    }

    const ull multp  = pack2(mult, mult);
    const ull negone = pack2(-1.0f, -1.0f);

    // 9 packed accumulators
    ull aa = 0ull, ab = 0ull, dd = 0ull;
    ull as0p = 0ull, as1p = 0ull, ssp = 0ull;
    ull as0n = 0ull, as1n = 0ull, ssn = 0ull;

    #pragma unroll
    for (int j = 0; j < 4; j++) {
        const ull HP = pack2(hp[2*j], hp[2*j+1]);
        const ull TP = pack2(tp[2*j], tp[2*j+1]);
        const ull HN = pack2(hn[2*j], hn[2*j+1]);
        const ull TN = pack2(tn[2*j], tn[2*j+1]);
        const ull HH = pack2(hh[2*j], hh[2*j+1]);
        const ull A0 = pack2(a0[2*j], a0[2*j+1]);
        const ull A1 = pack2(a1[2*j], a1[2*j+1]);
        const ull sv = ffma2(TP, negone, ffma2(HH, multp, HP));
        const ull nv = ffma2(TN, negone, ffma2(HH, multp, HN));
        aa   = ffma2(A0, A0, aa);
        ab   = ffma2(A0, A1, ab);
        dd   = ffma2(A1, A1, dd);
        as0p = ffma2(A0, sv, as0p);
        as1p = ffma2(A1, sv, as1p);
        ssp  = ffma2(sv, sv, ssp);
        as0n = ffma2(A0, nv, as0n);
        as1n = ffma2(A1, nv, as1n);
        ssn  = ffma2(nv, nv, ssn);
    }

    // Collapse packed pairs to 9 scalars
    float r_aa   = pair_sum(aa);
    float r_ab   = pair_sum(ab);
    float r_dd   = pair_sum(dd);
    float r_as0p = pair_sum(as0p);
    float r_as1p = pair_sum(as1p);
    float r_ssp  = pair_sum(ssp);
    float r_as0n = pair_sum(as0n);
    float r_as1n = pair_sum(as1n);
    float r_ssn  = pair_sum(ssn);

    // Fused butterfly allreduce of 9 scalars
    #pragma unroll
    for (int m = 16; m > 0; m >>= 1) {
        r_aa   += __shfl_xor_sync(0xffffffffu, r_aa,   m);
        r_ab   += __shfl_xor_sync(0xffffffffu, r_ab,   m);
        r_dd   += __shfl_xor_sync(0xffffffffu, r_dd,   m);
        r_as0p += __shfl_xor_sync(0xffffffffu, r_as0p, m);
        r_as1p += __shfl_xor_sync(0xffffffffu, r_as1p, m);
        r_ssp  += __shfl_xor_sync(0xffffffffu, r_ssp,  m);
        r_as0n += __shfl_xor_sync(0xffffffffu, r_as0n, m);
        r_as1n += __shfl_xor_sync(0xffffffffu, r_as1n, m);
        r_ssn  += __shfl_xor_sync(0xffffffffu, r_ssn,  m);
    }

    if (lane == 0) {
        const float det = r_aa * r_dd - r_ab * r_ab;
        float scp, scn;
        if (det != 0.0f) {
            // exact normal-equation solve -> ||proj||^2 = ss - c . As
            const float inv_det = 1.0f / det;
            const float c0p = ( r_dd * r_as0p - r_ab * r_as1p) * inv_det;
            const float c1p = (-r_ab * r_as0p + r_aa * r_as1p) * inv_det;
            const float c0n = ( r_dd * r_as0n - r_ab * r_as1n) * inv_det;
            const float c1n = (-r_ab * r_as0n + r_aa * r_as1n) * inv_det;
            scp = r_ssp - c0p * r_as0p - c1p * r_as1p;
            scn = r_ssn - c0n * r_as0n - c1n * r_as1n;
        } else {
            // fallback c = As / aa is NOT the exact solution -> full quadratic
            const float inv_a = 1.0f / r_aa;
            const float c0p = r_as0p * inv_a, c1p = r_as1p * inv_a;
            const float c0n = r_as0n * inv_a, c1n = r_as1n * inv_a;
            scp = r_ssp - 2.0f * (c0p * r_as0p + c1p * r_as1p)
                + c0p * c0p * r_aa + 2.0f * c0p * c1p * r_ab + c1p * c1p * r_dd;
            scn = r_ssn - 2.0f * (c0n * r_as0n + c1n * r_as1n)
                + c0n * c0n * r_aa + 2.0f * c0n * c1n * r_ab + c1n * c1n * r_dd;
        }
        out[warp]     = scp;
        out[B + warp] = scn;
    }
}

extern "C" void kernel_launch(void* const* d_in, const int* in_sizes, int n_in,
                              void* d_out, int out_size) {
    const int*   pos_h    = (const int*)  d_in[0];
    const int*   pos_t    = (const int*)  d_in[1];
    const int*   pos_r    = (const int*)  d_in[2];
    const int*   neg_h    = (const int*)  d_in[3];
    const int*   neg_t    = (const int*)  d_in[4];
    // d_in[5] = neg_r (unused by the reference)
    const float* ent_emb  = (const float*)d_in[6];
    const float* heads    = (const float*)d_in[7];
    const float* bases    = (const float*)d_in[8];
    const int*   rel2head = (const int*)  d_in[9];
    const float* rel2mult = (const float*)d_in[10];
    float* out = (float*)d_out;

    const int B = in_sizes[0];
    const int blocks = (B + WARPS_PER_BLOCK - 1) / WARPS_PER_BLOCK;
    transint_kernel<<<blocks, WARPS_PER_BLOCK * 32>>>(
        pos_h, pos_t, pos_r, neg_h, neg_t,
        ent_emb, heads, bases, rel2head, rel2mult, out, B);
}

// round 9
// speedup vs baseline: 1.0414x; 1.0414x over previous
#include <cuda_runtime.h>
#include <cuda_bf16.h>
#include <cstdint>

// TransINT scoring, single-pass quadratic form (R3 body) + L2 evict_last
// residency via createpolicy + ld.global.nc.L2::cache_hint. Working set
// (ent 100MB + bases 2MB + heads 0.1MB = 103MB) fits the 126MB L2: with
// evict_last, graph replays hit L2 instead of re-streaming from HBM.
//   re = heads[rel2head[r]] * rel2mult[r]        (r = pos_r; neg_r unused)
//   s_pos = ent[ph] + re - ent[pt];  s_neg = ent[nh] + re - ent[nt]
//   A = bases[r] (2 x 256); c = ATA^{-1} (A.s)
//   exact-solution identity: ||s - A^T c||^2 = s.s - c.(A.s)
// out[0:B) = pos, out[B:2B) = neg (float32)

#define D 256
#define WARPS_PER_BLOCK 8

__device__ __forceinline__ unsigned long long evict_last_policy() {
    unsigned long long p;
    asm("createpolicy.fractional.L2::evict_last.b64 %0, 1.0;" : "=l"(p));
    return p;
}

__device__ __forceinline__ float4 ldg_keep(const float4* p, unsigned long long pol) {
    float4 v;
    asm volatile("ld.global.nc.L2::cache_hint.v4.f32 {%0,%1,%2,%3}, [%4], %5;"
                 : "=f"(v.x), "=f"(v.y), "=f"(v.z), "=f"(v.w)
                 : "l"(p), "l"(pol));
    return v;
}

__global__ __launch_bounds__(WARPS_PER_BLOCK * 32, 5)
void transint_kernel(const int* __restrict__ pos_h,
                     const int* __restrict__ pos_t,
                     const int* __restrict__ pos_r,
                     const int* __restrict__ neg_h,
                     const int* __restrict__ neg_t,
                     const float* __restrict__ ent_emb,   // E x D
                     const float* __restrict__ heads,     // K x D
                     const float* __restrict__ bases,     // R x 2 x D
                     const int* __restrict__ rel2head,
                     const float* __restrict__ rel2mult,
                     float* __restrict__ out,
                     int B)
{
    const int warp = blockIdx.x * WARPS_PER_BLOCK + (threadIdx.x >> 5);
    if (warp >= B) return;
    const int lane = threadIdx.x & 31;

    // Per-sample indices (uniform across warp; broadcast loads)
    const int ph = pos_h[warp];
    const int pt = pos_t[warp];
    const int r  = pos_r[warp];
    const int nh = neg_h[warp];
    const int nt = neg_t[warp];
    const int hd = rel2head[r];
    const float mult = rel2mult[r];

    const unsigned long long pol = evict_last_policy();

    // Contiguous split: float4 index = lane and lane+32.
    // Each LDG.128 covers a 512B contiguous warp access.
    const int v0 = lane;
    const int v1 = lane + 32;

    const float4* __restrict__ Eph = (const float4*)(ent_emb + (size_t)ph * D);
    const float4* __restrict__ Ept = (const float4*)(ent_emb + (size_t)pt * D);
    const float4* __restrict__ Enh = (const float4*)(ent_emb + (size_t)nh * D);
    const float4* __restrict__ Ent = (const float4*)(ent_emb + (size_t)nt * D);
    const float4* __restrict__ Hd  = (const float4*)(heads   + (size_t)hd * D);
    const float4* __restrict__ A0p = (const float4*)(bases   + (size_t)r * 2 * D);
    const float4* __restrict__ A1p = (const float4*)(bases   + (size_t)r * 2 * D + D);

    // All 14 loads issued up-front (MLP covers L2 latency); L2 evict_last
    float4 hp0 = ldg_keep(Eph + v0, pol), hp1 = ldg_keep(Eph + v1, pol);
    float4 tp0 = ldg_keep(Ept + v0, pol), tp1 = ldg_keep(Ept + v1, pol);
    float4 hn0 = ldg_keep(Enh + v0, pol), hn1 = ldg_keep(Enh + v1, pol);
    float4 tn0 = ldg_keep(Ent + v0, pol), tn1 = ldg_keep(Ent + v1, pol);
    float4 re0 = ldg_keep(Hd  + v0, pol), re1 = ldg_keep(Hd  + v1, pol);
    float4 a00 = ldg_keep(A0p + v0, pol), a01 = ldg_keep(A0p + v1, pol);
    float4 a10 = ldg_keep(A1p + v0, pol), a11 = ldg_keep(A1p + v1, pol);

    // 9 streamed accumulators; no second pass over the data
    float aa = 0.f, ab = 0.f, dd = 0.f;
    float as0p = 0.f, as1p = 0.f, ssp = 0.f;
    float as0n = 0.f, as1n = 0.f, ssn = 0.f;

    {
        const float* hpp = (const float*)&hp0; const float* hpq = (const float*)&hp1;
        const float* tpp = (const float*)&tp0; const float* tpq = (const float*)&tp1;
        const float* hnp = (const float*)&hn0; const float* hnq = (const float*)&hn1;
        const float* tnp = (const float*)&tn0; const float* tnq = (const float*)&tn1;
        const float* rep = (const float*)&re0; const float* req = (const float*)&re1;
        const float* a0p = (const float*)&a00; const float* a0q = (const float*)&a01;
        const float* a1p = (const float*)&a10; const float* a1q = (const float*)&a11;
        #pragma unroll
        for (int i = 0; i < 4; i++) {
            {
                const float re = rep[i] * mult;
                const float sv = hpp[i] + re - tpp[i];
                const float nv = hnp[i] + re - tnp[i];
                const float A0 = a0p[i], A1 = a1p[i];
                aa   = fmaf(A0, A0, aa);
                ab   = fmaf(A0, A1, ab);
                dd   = fmaf(A1, A1, dd);
                as0p = fmaf(A0, sv, as0p);
                as1p = fmaf(A1, sv, as1p);
                ssp  = fmaf(sv, sv, ssp);
                as0n = fmaf(A0, nv, as0n);
                as1n = fmaf(A1, nv, as1n);
                ssn  = fmaf(nv, nv, ssn);
            }
            {
                const float re = req[i] * mult;
                const float sv = hpq[i] + re - tpq[i];
                const float nv = hnq[i] + re - tnq[i];
                const float A0 = a0q[i], A1 = a1q[i];
                aa   = fmaf(A0, A0, aa);
                ab   = fmaf(A0, A1, ab);
                dd   = fmaf(A1, A1, dd);
                as0p = fmaf(A0, sv, as0p);
                as1p = fmaf(A1, sv, as1p);
                ssp  = fmaf(sv, sv, ssp);
                as0n = fmaf(A0, nv, as0n);
                as1n = fmaf(A1, nv, as1n);
                ssn  = fmaf(nv, nv, ssn);
            }
        }
    }

    // Fused butterfly allreduce of 9 scalars
    #pragma unroll
    for (int m = 16; m > 0; m >>= 1) {
        aa   += __shfl_xor_sync(0xffffffffu, aa,   m);
        ab   += __shfl_xor_sync(0xffffffffu, ab,   m);
        dd   += __shfl_xor_sync(0xffffffffu, dd,   m);
        as0p += __shfl_xor_sync(0xffffffffu, as0p, m);
        as1p += __shfl_xor_sync(0xffffffffu, as1p, m);
        ssp  += __shfl_xor_sync(0xffffffffu, ssp,  m);
        as0n += __shfl_xor_sync(0xffffffffu, as0n, m);
        as1n += __shfl_xor_sync(0xffffffffu, as1n, m);
        ssn  += __shfl_xor_sync(0xffffffffu, ssn,  m);
    }

    if (lane == 0) {
        const float det = aa * dd - ab * ab;
        float scp, scn;
        if (det != 0.0f) {
            // exact normal-equation solve -> ||proj||^2 = ss - c . As
            const float inv_det = 1.0f / det;
            const float c0p = ( dd * as0p - ab * as1p) * inv_det;
            const float c1p = (-ab * as0p + aa * as1p) * inv_det;
            const float c0n = ( dd * as0n - ab * as1n) * inv_det;
            const float c1n = (-ab * as0n + aa * as1n) * inv_det;
            scp = ssp - c0p * as0p - c1p * as1p;
            scn = ssn - c0n * as0n - c1n * as1n;
        } else {
            // fallback c = As / aa is NOT the exact solution -> full quadratic
            const float inv_a = 1.0f / aa;
            const float c0p = as0p * inv_a, c1p = as1p * inv_a;
            const float c0n = as0n * inv_a, c1n = as1n * inv_a;
            scp = ssp - 2.0f * (c0p * as0p + c1p * as1p)
                + c0p * c0p * aa + 2.0f * c0p * c1p * ab + c1p * c1p * dd;
            scn = ssn - 2.0f * (c0n * as0n + c1n * as1n)
                + c0n * c0n * aa + 2.0f * c0n * c1n * ab + c1n * c1n * dd;
        }
        out[warp]     = scp;
        out[B + warp] = scn;
    }
}

extern "C" void kernel_launch(void* const* d_in, const int* in_sizes, int n_in,
                              void* d_out, int out_size) {
    const int*   pos_h    = (const int*)  d_in[0];
    const int*   pos_t    = (const int*)  d_in[1];
    const int*   pos_r    = (const int*)  d_in[2];
    const int*   neg_h    = (const int*)  d_in[3];
    const int*   neg_t    = (const int*)  d_in[4];
    // d_in[5] = neg_r (unused by the reference)
    const float* ent_emb  = (const float*)d_in[6];
    const float* heads    = (const float*)d_in[7];
    const float* bases    = (const float*)d_in[8];
    const int*   rel2head = (const int*)  d_in[9];
    const float* rel2mult = (const float*)d_in[10];
    float* out = (float*)d_out;

    const int B = in_sizes[0];
    const int blocks = (B + WARPS_PER_BLOCK - 1) / WARPS_PER_BLOCK;
    transint_kernel<<<blocks, WARPS_PER_BLOCK * 32>>>(
        pos_h, pos_t, pos_r, neg_h, neg_t,
        ent_emb, heads, bases, rel2head, rel2mult, out, B);
}